// round 3
// baseline (speedup 1.0000x reference)
#include <cuda_runtime.h>

// VectorQuantizer: inputs [131072, 64] f32, embeddings [512, 64] f32
// out (float32 buffer) = codes-as-float [131072]  ++  code_vecs f32 [131072*64]
//
// dist = (||x||^2 + ||e||^2) - 2 x.e computed with the SAME fp32 rounding
// structure as the reference (distance magnitude ~64, ulp ~7.6e-6) so that
// near-tie rows resolve identically (equal fp32 -> lowest index).

#define XS_STRIDE 129   // float4 units per dseg row (padded: 128 rows + 1)
#define SMEM_BYTES ((16 * XS_STRIDE + 512 * 16) * 16 + 512 * 4 + 128 * 4)

__device__ __forceinline__ void fma2(unsigned long long &acc,
                                     unsigned long long a,
                                     unsigned long long b) {
    asm("fma.rn.f32x2 %0, %1, %2, %0;" : "+l"(acc) : "l"(a), "l"(b));
}

__device__ __forceinline__ float2 unpack2(unsigned long long v) {
    float2 r;
    asm("mov.b64 {%0, %1}, %2;" : "=f"(r.x), "=f"(r.y) : "l"(v));
    return r;
}

__global__ __launch_bounds__(256, 1)
void vq_argmin_kernel(const float4* __restrict__ in4,    // [nrows][16] f4
                      const float4* __restrict__ emb4,   // [512][16] f4
                      float* __restrict__ codes_out,     // [nrows] (as float)
                      float4* __restrict__ vecs_out)     // [nrows][16] f4
{
    extern __shared__ char smem[];
    float4* xs  = (float4*)smem;                // [16 dseg][XS_STRIDE rows] f4
    float4* es  = xs + 16 * XS_STRIDE;          // [512 codes][16 dseg] f4
    float*  e2  = (float*)(es + 512 * 16);      // [512] ||e||^2
    float*  l2r = e2 + 512;                     // [128] ||x||^2 per row
    // reused after main loop:
    float* redv  = (float*)smem;                // [8 ct][128 rows]
    int*   redi  = (int*)(smem + 4096);         // [8 ct][128 rows]
    int*   rcode = (int*)e2;                    // [128] final code per row

    const int tid  = threadIdx.x;
    const int row0 = blockIdx.x * 128;

    // ---- load 128-row input tile, transposed to [dseg][row] ----
    #pragma unroll
    for (int i = 0; i < 8; ++i) {
        int idx  = tid + i * 256;       // 0..2047
        int dseg = idx & 15;
        int r    = idx >> 4;
        xs[dseg * XS_STRIDE + r] = in4[(size_t)(row0 + r) * 16 + dseg];
    }
    // ---- load full embedding table ----
    #pragma unroll
    for (int i = 0; i < 32; ++i) {
        int idx = tid + i * 256;
        es[idx] = emb4[idx];
    }
    __syncthreads();

    // ---- e2[c] = ||e_c||^2 (full, fp32) ----
    #pragma unroll
    for (int i = 0; i < 2; ++i) {
        int c = tid + i * 256;
        const float4* ep = es + c * 16;
        float s = 0.0f;
        #pragma unroll
        for (int j = 0; j < 16; ++j) {
            float4 v = ep[j];
            s += v.x * v.x + v.y * v.y + v.z * v.z + v.w * v.w;
        }
        e2[c] = s;
    }
    // ---- l2r[r] = ||x_r||^2 (fp32, per-row constant) ----
    if (tid < 128) {
        float s = 0.0f;
        #pragma unroll
        for (int j = 0; j < 16; ++j) {
            float4 v = xs[j * XS_STRIDE + tid];
            s += v.x * v.x + v.y * v.y + v.z * v.z + v.w * v.w;
        }
        l2r[tid] = s;
    }
    __syncthreads();

    const int rt = tid & 31;   // row thread: rows rt, rt+32, rt+64, rt+96
    const int ct = tid >> 5;   // code thread: 8 codes per step

    float bestd[4];
    int   besti[4];
    float myl2[4];
    #pragma unroll
    for (int rr = 0; rr < 4; ++rr) {
        bestd[rr] = 3.4e38f; besti[rr] = 0;
        myl2[rr]  = l2r[rt + 32 * rr];
    }

    const ulonglong2* xs2 = (const ulonglong2*)xs;
    const ulonglong2* es2 = (const ulonglong2*)es;

    // ---- main loop: 8 code steps x 64 codes ----
    for (int cs = 0; cs < 8; ++cs) {
        const int c0 = cs * 64 + ct * 8;

        unsigned long long acc[4][8];
        #pragma unroll
        for (int rr = 0; rr < 4; ++rr)
            #pragma unroll
            for (int cc = 0; cc < 8; ++cc)
                acc[rr][cc] = 0ull;   // f32x2 (0,0)

        #pragma unroll 4
        for (int dseg = 0; dseg < 16; ++dseg) {
            ulonglong2 xv[4];
            #pragma unroll
            for (int rr = 0; rr < 4; ++rr)
                xv[rr] = xs2[dseg * XS_STRIDE + rt + 32 * rr];
            ulonglong2 ev[8];
            #pragma unroll
            for (int cc = 0; cc < 8; ++cc)
                ev[cc] = es2[(c0 + cc) * 16 + dseg];   // warp broadcast
            #pragma unroll
            for (int rr = 0; rr < 4; ++rr)
                #pragma unroll
                for (int cc = 0; cc < 8; ++cc) {
                    fma2(acc[rr][cc], xv[rr].x, ev[cc].x);
                    fma2(acc[rr][cc], xv[rr].y, ev[cc].y);
                }
        }

        // finalize distances for this step with reference-matching rounding:
        // t = fp32(l2x + e2[c]);  dist = fp32(t - 2*s)   (2*s exact)
        #pragma unroll
        for (int cc = 0; cc < 8; ++cc) {
            const int   c  = c0 + cc;
            const float eh = e2[c];
            #pragma unroll
            for (int rr = 0; rr < 4; ++rr) {
                float2 p = unpack2(acc[rr][cc]);
                float  s = p.x + p.y;
                float  t = myl2[rr] + eh;
                float dist = t - 2.0f * s;
                if (dist < bestd[rr]) { bestd[rr] = dist; besti[rr] = c; }
            }
        }
    }

    __syncthreads();   // done reading xs; reuse for reduction

    #pragma unroll
    for (int rr = 0; rr < 4; ++rr) {
        int r = rt + 32 * rr;
        redv[ct * 128 + r] = bestd[rr];
        redi[ct * 128 + r] = besti[rr];
    }
    __syncthreads();

    if (tid < 128) {
        float bv = redv[tid];
        int   bi = redi[tid];
        #pragma unroll
        for (int j = 1; j < 8; ++j) {
            float v  = redv[j * 128 + tid];
            int   ii = redi[j * 128 + tid];
            if (v < bv || (v == bv && ii < bi)) { bv = v; bi = ii; }
        }
        rcode[tid] = bi;
        codes_out[row0 + tid] = (float)bi;   // codes as FLOAT values
    }
    __syncthreads();

    // ---- gather code vectors from smem embeddings ----
    #pragma unroll
    for (int i = 0; i < 8; ++i) {
        int idx  = tid + i * 256;
        int r    = idx >> 4;
        int dseg = idx & 15;
        vecs_out[(size_t)(row0 + r) * 16 + dseg] = es[rcode[r] * 16 + dseg];
    }
}

extern "C" void kernel_launch(void* const* d_in, const int* in_sizes, int n_in,
                              void* d_out, int out_size)
{
    const int nrows = in_sizes[0] / 64;            // 131072
    const int nblocks = nrows / 128;               // 1024

    cudaFuncSetAttribute(vq_argmin_kernel,
                         cudaFuncAttributeMaxDynamicSharedMemorySize,
                         SMEM_BYTES);

    float*  codes = (float*)d_out;
    float4* vecs  = (float4*)((float*)d_out + nrows);

    vq_argmin_kernel<<<nblocks, 256, SMEM_BYTES>>>(
        (const float4*)d_in[0],
        (const float4*)d_in[1],
        codes, vecs);
}